// round 5
// baseline (speedup 1.0000x reference)
#include <cuda_runtime.h>
#include <cuda_bf16.h>

// Problem constants
#define NN    1024
#define II    64
#define RTAIL 960          // N - I
#define TAILK 896          // rows 128..1023
#define NWARM 25
#define NB    60           // warm blocks (all co-resident)
#define COLSB 16           // tail columns per warm block (2 per warp)
#define BROWS 16384

// ---------------- device scratch (static: no allocations allowed) -------------
__device__ float d_W64[64 * 1024];       // (delta/N)*sig_diff[k<64][64+j], pad j<1024
__device__ float d_C[1024];              // per-column constant, padded zeros
__device__ float d_ubuf[2][RTAIL];       // unnormalized warmup state ping-pong
__device__ float d_spart[2][NB];         // per-block partial sums (ping-pong)
__device__ unsigned d_stamp[NB];         // per-block publish counters
__device__ float d_rowpart[8 * BROWS];   // per-chunk row-sum partials
__device__ unsigned g_barcnt = 0;
__device__ unsigned g_bargen = 0;

// ---------------- helpers ----------------------------------------------------
static __device__ __forceinline__ float sigd(float idv, float e, float iv, float b) {
    return expf(-b * fabsf(e - idv)) - expf(-b * fabsf(iv - idv));
}

static __device__ __forceinline__ void grid_barrier(int nb) {
    __threadfence();
    __syncthreads();
    if (threadIdx.x == 0) {
        unsigned gen = *(volatile unsigned*)&g_bargen;
        unsigned arrived = atomicAdd(&g_barcnt, 1u);
        if (arrived == (unsigned)(nb - 1)) {
            g_barcnt = 0;
            __threadfence();
            atomicAdd(&g_bargen, 1u);
        } else {
            while (*(volatile unsigned*)&g_bargen == gen) { }
            __threadfence();
        }
    }
    __syncthreads();
}

static __device__ __forceinline__ unsigned long long splat2(float x) {
    unsigned long long d;
    asm("mov.b64 %0, {%1, %1};" : "=l"(d) : "f"(x));
    return d;
}
static __device__ __forceinline__ unsigned long long ffma2(unsigned long long a,
                                                           unsigned long long b,
                                                           unsigned long long c) {
    unsigned long long d;
    asm("fma.rn.f32x2 %0, %1, %2, %3;" : "=l"(d) : "l"(a), "l"(b), "l"(c));
    return d;
}
static __device__ __forceinline__ void unpack2(unsigned long long v, float& lo, float& hi) {
    asm("mov.b64 {%0, %1}, %2;" : "=f"(lo), "=f"(hi) : "l"(v));
}

static __device__ __forceinline__ float warp_sum(float v) {
    #pragma unroll
    for (int o = 16; o; o >>= 1) v += __shfl_xor_sync(0xffffffffu, v, o);
    return v;
}

// ---------------- kernel 1: warmup with stamp-based sync ----------------------
// 60 blocks x 256 threads; each warp owns 2 tail columns, w-slice in registers.
__global__ void __launch_bounds__(256)
warm_kernel(const float* __restrict__ ids, const float* __restrict__ enh,
            const float* __restrict__ inh, const float* __restrict__ beta,
            const float* __restrict__ delta) {
    __shared__ float red8[8];

    const float b  = beta[0];
    const float dn = delta[0] * (1.0f / (float)NN);
    const int tid  = threadIdx.x;
    const int bid  = blockIdx.x;
    const int warp = tid >> 5;
    const int lane = tid & 31;
    const int j0   = bid * COLSB;
    const int c0   = warp * 2, c1 = c0 + 1;

    if (tid == 0) *(volatile unsigned*)&d_stamp[bid] = 0u;

    // --- W64 fill (pre-scaled, cols 960..1023 zero-padded) -------------------
    for (int idx = bid * 256 + tid; idx < 64 * 1024; idx += NB * 256) {
        int k = idx >> 10, j = idx & 1023;
        float v = 0.f;
        if (j < RTAIL) v = dn * sigd(ids[II + j], enh[k], inh[k], b);
        d_W64[idx] = v;
    }

    // --- head terms h for my 2 columns ---------------------------------------
    const float idv0 = ids[II + j0 + c0];
    const float idv1 = ids[II + j0 + c1];
    float h0 = sigd(idv0, enh[lane], inh[lane], b)
             + sigd(idv0, enh[lane + 32], inh[lane + 32], b);
    float h1 = sigd(idv1, enh[lane], inh[lane], b)
             + sigd(idv1, enh[lane + 32], inh[lane + 32], b);
    h0 = warp_sum(h0) * (1.0f / (float)NN);
    h1 = warp_sum(h1) * (1.0f / (float)NN);

    // --- register-resident w slices (rows 128..1023) -------------------------
    float w0[28], w1[28];
    #pragma unroll
    for (int q = 0; q < 28; ++q) {
        int i = 128 + lane + 32 * q;
        float e = enh[i], iv = inh[i];
        w0[q] = sigd(idv0, e, iv, b);
        w1[q] = sigd(idv1, e, iv, b);
    }

    // --- init state + zero C padding -----------------------------------------
    {
        int g = bid * 256 + tid;
        if (g < RTAIL) d_ubuf[0][g] = 1.0f / (float)NN;
        if (bid == 0 && tid < 64) d_C[RTAIL + tid] = 0.f;
    }
    grid_barrier(NB);   // once: init + W64 + stamp zeros visible everywhere

    float pu0 = 1.0f / (float)NN, pu1 = pu0;   // this block's own u values

    for (int it = 0; it < NWARM; ++it) {
        const int p = it & 1;
        if (it > 0) {
            if (warp == 0) {
                volatile unsigned* st = d_stamp;
                for (;;) {
                    unsigned m1 = st[lane];
                    unsigned m2 = (lane < NB - 32) ? st[lane + 32] : 0xffffffffu;
                    if (__all_sync(0xffffffffu,
                                   m1 >= (unsigned)it && m2 >= (unsigned)it)) break;
                }
                __threadfence();
            }
            __syncthreads();
        }

        // inv = 1/s from per-block partials (it==0: reference uses raw conc)
        float inv = 1.0f;
        if (it > 0) {
            float sv = (lane < NB) ? __ldcg(&d_spart[p][lane]) : 0.f;
            if (lane < NB - 32) sv += __ldcg(&d_spart[p][lane + 32]);
            float s = warp_sum(sv);
            inv = (s > 0.f) ? 1.0f / s : 1.0f;
        }

        // dots over tail rows: u from L2 (ldcg), w from registers
        const float* up = d_ubuf[p];
        float d0 = 0.f, d1 = 0.f;
        #pragma unroll
        for (int q = 0; q < 28; ++q) {
            float u = __ldcg(&up[64 + lane + 32 * q]);
            d0 = fmaf(u, w0[q], d0);
            d1 = fmaf(u, w1[q], d1);
        }
        d0 = warp_sum(d0);
        d1 = warp_sum(d1);

        if (lane == 0) {
            float nv0 = fmaxf(pu0 * inv + dn * (h0 + d0 * inv), 0.f);
            float nv1 = fmaxf(pu1 * inv + dn * (h1 + d1 * inv), 0.f);
            d_ubuf[p ^ 1][j0 + c0] = nv0;
            d_ubuf[p ^ 1][j0 + c1] = nv1;
            pu0 = nv0; pu1 = nv1;
            red8[warp] = nv0 + nv1;
        }
        __syncthreads();
        if (tid == 0) {
            float bs = red8[0] + red8[1] + red8[2] + red8[3]
                     + red8[4] + red8[5] + red8[6] + red8[7];
            d_spart[p ^ 1][bid] = bs;
            __threadfence();
            *(volatile unsigned*)&d_stamp[bid] = (unsigned)(it + 1);
        }
    }

    // --- final: C_j = u_j*inv + dn * dot(u)*inv ------------------------------
    {
        const int p = NWARM & 1;
        if (warp == 0) {
            volatile unsigned* st = d_stamp;
            for (;;) {
                unsigned m1 = st[lane];
                unsigned m2 = (lane < NB - 32) ? st[lane + 32] : 0xffffffffu;
                if (__all_sync(0xffffffffu,
                               m1 >= (unsigned)NWARM && m2 >= (unsigned)NWARM)) break;
            }
            __threadfence();
        }
        __syncthreads();

        float sv = (lane < NB) ? __ldcg(&d_spart[p][lane]) : 0.f;
        if (lane < NB - 32) sv += __ldcg(&d_spart[p][lane + 32]);
        float s = warp_sum(sv);
        float inv = (s > 0.f) ? 1.0f / s : 1.0f;

        const float* up = d_ubuf[p];
        float d0 = 0.f, d1 = 0.f;
        #pragma unroll
        for (int q = 0; q < 28; ++q) {
            float u = __ldcg(&up[64 + lane + 32 * q]);
            d0 = fmaf(u, w0[q], d0);
            d1 = fmaf(u, w1[q], d1);
        }
        d0 = warp_sum(d0);
        d1 = warp_sum(d1);

        if (lane == 0) {
            d_C[j0 + c0] = pu0 * inv + dn * d0 * inv;
            d_C[j0 + c1] = pu1 * inv + dn * d1 * inv;
        }
    }
}

// ---------------- kernel 2: GEMM, grid = (row tiles, 8 col chunks) -----------
#define TM 128
#define AS_STRIDE 132
#define SMEM_GEMM ((64 * AS_STRIDE + 64 * AS_STRIDE) * 4)

__global__ void __launch_bounds__(256)
gemm_kernel(const float* __restrict__ inp, float* __restrict__ out) {
    extern __shared__ float sm[];
    float* As = sm;                      // [64][132]  A^T: As[k][row]
    float* Ws = As + 64 * AS_STRIDE;     // [64][132]  chunk of W64

    const int tid = threadIdx.x;
    const int tx = tid & 15, ty = tid >> 4;
    const int b0 = blockIdx.x * TM;
    const int chunk = blockIdx.y;
    const int cbase = chunk * 128;

    for (int idx = tid; idx < TM * 64; idx += 256) {
        int row = idx >> 6, k = idx & 63;
        As[k * AS_STRIDE + row] = inp[(b0 + row) * 64 + k];
    }
    for (int idx = tid; idx < 64 * 128; idx += 256) {
        int k = idx >> 7, j = idx & 127;
        Ws[k * AS_STRIDE + j] = d_W64[k * 1024 + cbase + j];
    }
    __syncthreads();

    unsigned long long acc[8][4];
    #pragma unroll
    for (int r = 0; r < 8; ++r)
        #pragma unroll
        for (int c = 0; c < 4; ++c) acc[r][c] = 0ull;

    #pragma unroll 4
    for (int k = 0; k < 64; ++k) {
        float4 a0 = *(const float4*)&As[k * AS_STRIDE + ty * 8];
        float4 a1 = *(const float4*)&As[k * AS_STRIDE + ty * 8 + 4];
        ulonglong2 w01 = *(const ulonglong2*)&Ws[k * AS_STRIDE + tx * 8];
        ulonglong2 w23 = *(const ulonglong2*)&Ws[k * AS_STRIDE + tx * 8 + 4];
        unsigned long long sp[8];
        sp[0] = splat2(a0.x); sp[1] = splat2(a0.y);
        sp[2] = splat2(a0.z); sp[3] = splat2(a0.w);
        sp[4] = splat2(a1.x); sp[5] = splat2(a1.y);
        sp[6] = splat2(a1.z); sp[7] = splat2(a1.w);
        #pragma unroll
        for (int r = 0; r < 8; ++r) {
            acc[r][0] = ffma2(sp[r], w01.x, acc[r][0]);
            acc[r][1] = ffma2(sp[r], w01.y, acc[r][1]);
            acc[r][2] = ffma2(sp[r], w23.x, acc[r][2]);
            acc[r][3] = ffma2(sp[r], w23.y, acc[r][3]);
        }
    }

    float cv[8];
    #pragma unroll
    for (int cc = 0; cc < 8; ++cc) cv[cc] = d_C[cbase + tx * 8 + cc];
    const bool store0 = (chunk == 0) && (tx < 8);

    float s_part[8];
    #pragma unroll
    for (int r = 0; r < 8; ++r) {
        int row = ty * 8 + r;
        float sp_r = 0.f;
        #pragma unroll
        for (int cp = 0; cp < 4; ++cp) {
            float lo, hi;
            unpack2(acc[r][cp], lo, hi);
            float v0 = fmaxf(cv[cp * 2] + lo, 0.f);
            float v1 = fmaxf(cv[cp * 2 + 1] + hi, 0.f);
            sp_r += v0 + v1;
            if (store0) {
                out[(b0 + row) * 64 + tx * 8 + cp * 2]     = v0;
                out[(b0 + row) * 64 + tx * 8 + cp * 2 + 1] = v1;
            }
        }
        s_part[r] = sp_r;
    }
    #pragma unroll
    for (int r = 0; r < 8; ++r) {
        #pragma unroll
        for (int m = 8; m; m >>= 1)
            s_part[r] += __shfl_xor_sync(0xffffffffu, s_part[r], m, 16);
    }
    if (tx == 0) {
        #pragma unroll
        for (int r = 0; r < 8; ++r)
            d_rowpart[chunk * BROWS + b0 + ty * 8 + r] = s_part[r];
    }
}

// ---------------- kernel 3: normalize rows (in-place on out) -----------------
__global__ void __launch_bounds__(256)
scale_kernel(float* __restrict__ out) {
    __shared__ float inv_s[256];
    const int tid = threadIdx.x;
    const int base = blockIdx.x * 256;

    float s = 0.f;
    #pragma unroll
    for (int c = 0; c < 8; ++c) s += d_rowpart[c * BROWS + base + tid];
    inv_s[tid] = (s > 0.f) ? 1.0f / s : 1.0f;
    __syncthreads();

    for (int idx = tid; idx < 256 * 64; idx += 256) {
        int r = idx >> 6;
        out[base * 64 + idx] *= inv_s[r];
    }
}

// ---------------- launch ------------------------------------------------------
extern "C" void kernel_launch(void* const* d_in, const int* in_sizes, int n_in,
                              void* d_out, int out_size) {
    const float* inputs = (const float*)d_in[0];
    const float* ids    = (const float*)d_in[1];
    const float* enh    = (const float*)d_in[2];
    const float* inh    = (const float*)d_in[3];
    const float* beta   = (const float*)d_in[4];
    const float* delta  = (const float*)d_in[5];

    cudaFuncSetAttribute(gemm_kernel, cudaFuncAttributeMaxDynamicSharedMemorySize,
                         SMEM_GEMM);

    warm_kernel<<<NB, 256>>>(ids, enh, inh, beta, delta);

    dim3 grid(BROWS / TM, 8);
    gemm_kernel<<<grid, 256, SMEM_GEMM>>>(inputs, (float*)d_out);

    scale_kernel<<<BROWS / 256, 256>>>((float*)d_out);
}

// round 6
// speedup vs baseline: 1.2784x; 1.2784x over previous
#include <cuda_runtime.h>
#include <cuda_bf16.h>

// Problem constants
#define NN    1024
#define II    64
#define RTAIL 960          // N - I
#define TAILK 896          // rows 128..1023
#define NWARM 25
#define CB    16           // warm cluster size == grid size
#define JB    60           // tail columns per warm block (16*60 = 960)
#define BROWS 16384

// ---------------- device scratch (static: no allocations allowed) -------------
__device__ float d_W64[64 * 1024];       // (delta/N)*sig_diff[k<64][64+j], pad j<1024
__device__ float d_C[1024];              // per-column constant, padded zeros
__device__ float d_rowpart[8 * BROWS];   // per-chunk row-sum partials

// ---------------- helpers ----------------------------------------------------
static __device__ __forceinline__ float sigd(float idv, float e, float iv, float b) {
    return expf(-b * fabsf(e - idv)) - expf(-b * fabsf(iv - idv));
}
static __device__ __forceinline__ unsigned long long splat2(float x) {
    unsigned long long d;
    asm("mov.b64 %0, {%1, %1};" : "=l"(d) : "f"(x));
    return d;
}
static __device__ __forceinline__ unsigned long long ffma2(unsigned long long a,
                                                           unsigned long long b,
                                                           unsigned long long c) {
    unsigned long long d;
    asm("fma.rn.f32x2 %0, %1, %2, %3;" : "=l"(d) : "l"(a), "l"(b), "l"(c));
    return d;
}
static __device__ __forceinline__ void unpack2(unsigned long long v, float& lo, float& hi) {
    asm("mov.b64 {%0, %1}, %2;" : "=f"(lo), "=f"(hi) : "l"(v));
}
static __device__ __forceinline__ float warp_sum(float v) {
    #pragma unroll
    for (int o = 16; o; o >>= 1) v += __shfl_xor_sync(0xffffffffu, v, o);
    return v;
}
static __device__ __forceinline__ unsigned smem_u32(const void* p) {
    unsigned a;
    asm("{ .reg .u64 t; cvta.to.shared.u64 t, %1; cvt.u32.u64 %0, t; }"
        : "=r"(a) : "l"(p));
    return a;
}
static __device__ __forceinline__ void cluster_sync_hw() {
    asm volatile("barrier.cluster.arrive.aligned;" ::: "memory");
    asm volatile("barrier.cluster.wait.aligned;"   ::: "memory");
}
static __device__ __forceinline__ float dsmem_ld(unsigned local_addr, int rank) {
    unsigned rem;
    asm("mapa.shared::cluster.u32 %0, %1, %2;" : "=r"(rem) : "r"(local_addr), "r"(rank));
    float v;
    asm volatile("ld.shared::cluster.f32 %0, [%1];" : "=f"(v) : "r"(rem));
    return v;
}

// ---------------- warm kernel smem layout (floats) ----------------------------
#define OFF_U   (JB * TAILK)          // 53760: u_s[960]
#define OFF_H   (OFF_U + RTAIL)       // 54720: h_s[60] (+pad)
#define OFF_XB  (OFF_H + 64)          // 54784: xbuf[2][60]
#define OFF_RED (OFF_XB + 2 * JB)     // 54904: red[8]
#define WARM_FLOATS (OFF_RED + 8)     // 54912
#define WARM_SMEM (WARM_FLOATS * 4)   // 219,648 B

// ---------------- kernel 1: clustered warmup ----------------------------------
__global__ void __launch_bounds__(256, 1) __cluster_dims__(CB, 1, 1)
warm_kernel(const float* __restrict__ ids, const float* __restrict__ enh,
            const float* __restrict__ inh, const float* __restrict__ beta,
            const float* __restrict__ delta) {
    extern __shared__ float sm[];
    float* w_s = sm;              // [60][896] this block's weight slice
    float* u_s = sm + OFF_U;      // [960] full tail state (local copy)
    float* h_s = sm + OFF_H;      // [60] head terms
    float* xb  = sm + OFF_XB;     // [2][60] exchange double buffer
    float* red = sm + OFF_RED;    // [8]

    const float b  = beta[0];
    const float dn = delta[0] * (1.0f / (float)NN);
    const int tid  = threadIdx.x;
    const int bid  = blockIdx.x;          // == cluster rank (grid == cluster)
    const int warp = tid >> 5;
    const int lane = tid & 31;
    const int j0   = bid * JB;

    // --- setup: W64 global fill (for gemm) -----------------------------------
    for (int idx = bid * 256 + tid; idx < 64 * 1024; idx += CB * 256) {
        int k = idx >> 10, j = idx & 1023;
        float v = 0.f;
        if (j < RTAIL) v = dn * sigd(ids[II + j], enh[k], inh[k], b);
        d_W64[idx] = v;
    }
    // --- setup: local weight slice w_s[c][i], c<60, rows 128..1023 -----------
    for (int idx = tid; idx < JB * TAILK; idx += 256) {
        int c = idx / TAILK, i = idx - c * TAILK;
        w_s[idx] = sigd(ids[II + j0 + c], enh[128 + i], inh[128 + i], b);
    }
    // --- setup: head terms h_s[c] --------------------------------------------
    for (int c = warp; c < JB; c += 8) {
        float idv = ids[II + j0 + c];
        float hv = sigd(idv, enh[lane], inh[lane], b)
                 + sigd(idv, enh[lane + 32], inh[lane + 32], b);
        hv = warp_sum(hv);
        if (lane == 0) h_s[c] = hv * (1.0f / (float)NN);
    }
    // --- setup: u = 1/N, C padding -------------------------------------------
    for (int i = tid; i < RTAIL; i += 256) u_s[i] = 1.0f / (float)NN;
    if (bid == 0 && tid < 64) d_C[RTAIL + tid] = 0.f;
    __syncthreads();

    // column ownership: warps 0-3 -> 8 cols, warps 4-7 -> 7 cols (total 60)
    const int nc = (warp < 4) ? 8 : 7;
    const int cbse = (warp < 4) ? warp * 8 : 32 + (warp - 4) * 7;
    const float* wp = &w_s[cbse * TAILK];

    float inv = 1.0f;   // it==0: reference applies step to raw conc0
    for (int it = 0; it < NWARM; ++it) {
        const int buf = it & 1;

        // ---- dots for my columns (LDS-bound) --------------------------------
        float acc[8];
        #pragma unroll
        for (int c = 0; c < 8; ++c) acc[c] = 0.f;
        #pragma unroll 4
        for (int q = 0; q < 28; ++q) {
            const int off = lane + 32 * q;
            float u = u_s[64 + off];
            #pragma unroll
            for (int c = 0; c < 8; ++c)
                acc[c] = fmaf(u, wp[c * TAILK + off], acc[c]);
        }
        #pragma unroll
        for (int c = 0; c < 8; ++c) {
            float dsum = warp_sum(acc[c]);
            if (lane == 0 && c < nc) {
                int cl = cbse + c;
                float uo = u_s[j0 + cl];
                float nv = fmaxf(uo * inv + dn * (h_s[cl] + dsum * inv), 0.f);
                xb[buf * JB + cl] = nv;
            }
        }

        // ---- cluster barrier: all new u published in peers' smem ------------
        cluster_sync_hw();

        // ---- gather full u from all 16 CTAs via DSMEM; local s reduce -------
        float p = 0.f;
        const unsigned xb_base = smem_u32(&xb[buf * JB]);
        #pragma unroll
        for (int r = 0; r < 4; ++r) {
            int i = tid + 256 * r;
            if (i < RTAIL) {
                int owner = i / JB;
                int slot  = i - owner * JB;
                float v = dsmem_ld(xb_base + slot * 4, owner);
                u_s[i] = v;
                p += v;
            }
        }
        p = warp_sum(p);
        if (lane == 0) red[warp] = p;
        __syncthreads();
        float s = red[0] + red[1] + red[2] + red[3]
                + red[4] + red[5] + red[6] + red[7];
        inv = (s > 0.f) ? 1.0f / s : 1.0f;
        // next write to red / u_s is separated by the next cluster_sync
    }

    // ---- final: C_j = u_j*inv + dn*dot(u)*inv (no head term; gemm adds it) --
    {
        float acc[8];
        #pragma unroll
        for (int c = 0; c < 8; ++c) acc[c] = 0.f;
        #pragma unroll 4
        for (int q = 0; q < 28; ++q) {
            const int off = lane + 32 * q;
            float u = u_s[64 + off];
            #pragma unroll
            for (int c = 0; c < 8; ++c)
                acc[c] = fmaf(u, wp[c * TAILK + off], acc[c]);
        }
        #pragma unroll
        for (int c = 0; c < 8; ++c) {
            float dsum = warp_sum(acc[c]);
            if (lane == 0 && c < nc) {
                int cl = cbse + c;
                d_C[j0 + cl] = u_s[j0 + cl] * inv + dn * dsum * inv;
            }
        }
    }
    cluster_sync_hw();   // no CTA exits while peers may still DSMEM-read
}

// ---------------- kernel 2: GEMM, grid = (row tiles, 8 col chunks) -----------
#define TM 128
#define AS_STRIDE 132
#define SMEM_GEMM ((64 * AS_STRIDE + 64 * AS_STRIDE) * 4)

__global__ void __launch_bounds__(256)
gemm_kernel(const float* __restrict__ inp, float* __restrict__ out) {
    extern __shared__ float sm[];
    float* As = sm;                      // [64][132]  A^T: As[k][row]
    float* Ws = As + 64 * AS_STRIDE;     // [64][132]  chunk of W64

    const int tid = threadIdx.x;
    const int tx = tid & 15, ty = tid >> 4;
    const int b0 = blockIdx.x * TM;
    const int chunk = blockIdx.y;
    const int cbase = chunk * 128;

    for (int idx = tid; idx < TM * 64; idx += 256) {
        int row = idx >> 6, k = idx & 63;
        As[k * AS_STRIDE + row] = inp[(b0 + row) * 64 + k];
    }
    for (int idx = tid; idx < 64 * 128; idx += 256) {
        int k = idx >> 7, j = idx & 127;
        Ws[k * AS_STRIDE + j] = d_W64[k * 1024 + cbase + j];
    }
    __syncthreads();

    unsigned long long acc[8][4];
    #pragma unroll
    for (int r = 0; r < 8; ++r)
        #pragma unroll
        for (int c = 0; c < 4; ++c) acc[r][c] = 0ull;

    #pragma unroll 4
    for (int k = 0; k < 64; ++k) {
        float4 a0 = *(const float4*)&As[k * AS_STRIDE + ty * 8];
        float4 a1 = *(const float4*)&As[k * AS_STRIDE + ty * 8 + 4];
        ulonglong2 w01 = *(const ulonglong2*)&Ws[k * AS_STRIDE + tx * 8];
        ulonglong2 w23 = *(const ulonglong2*)&Ws[k * AS_STRIDE + tx * 8 + 4];
        unsigned long long sp[8];
        sp[0] = splat2(a0.x); sp[1] = splat2(a0.y);
        sp[2] = splat2(a0.z); sp[3] = splat2(a0.w);
        sp[4] = splat2(a1.x); sp[5] = splat2(a1.y);
        sp[6] = splat2(a1.z); sp[7] = splat2(a1.w);
        #pragma unroll
        for (int r = 0; r < 8; ++r) {
            acc[r][0] = ffma2(sp[r], w01.x, acc[r][0]);
            acc[r][1] = ffma2(sp[r], w01.y, acc[r][1]);
            acc[r][2] = ffma2(sp[r], w23.x, acc[r][2]);
            acc[r][3] = ffma2(sp[r], w23.y, acc[r][3]);
        }
    }

    float cv[8];
    #pragma unroll
    for (int cc = 0; cc < 8; ++cc) cv[cc] = d_C[cbase + tx * 8 + cc];
    const bool store0 = (chunk == 0) && (tx < 8);

    float s_part[8];
    #pragma unroll
    for (int r = 0; r < 8; ++r) {
        int row = ty * 8 + r;
        float sp_r = 0.f;
        #pragma unroll
        for (int cp = 0; cp < 4; ++cp) {
            float lo, hi;
            unpack2(acc[r][cp], lo, hi);
            float v0 = fmaxf(cv[cp * 2] + lo, 0.f);
            float v1 = fmaxf(cv[cp * 2 + 1] + hi, 0.f);
            sp_r += v0 + v1;
            if (store0) {
                out[(b0 + row) * 64 + tx * 8 + cp * 2]     = v0;
                out[(b0 + row) * 64 + tx * 8 + cp * 2 + 1] = v1;
            }
        }
        s_part[r] = sp_r;
    }
    #pragma unroll
    for (int r = 0; r < 8; ++r) {
        #pragma unroll
        for (int m = 8; m; m >>= 1)
            s_part[r] += __shfl_xor_sync(0xffffffffu, s_part[r], m, 16);
    }
    if (tx == 0) {
        #pragma unroll
        for (int r = 0; r < 8; ++r)
            d_rowpart[chunk * BROWS + b0 + ty * 8 + r] = s_part[r];
    }
}

// ---------------- kernel 3: normalize rows (in-place on out) -----------------
__global__ void __launch_bounds__(256)
scale_kernel(float* __restrict__ out) {
    __shared__ float inv_s[256];
    const int tid = threadIdx.x;
    const int base = blockIdx.x * 256;

    float s = 0.f;
    #pragma unroll
    for (int c = 0; c < 8; ++c) s += d_rowpart[c * BROWS + base + tid];
    inv_s[tid] = (s > 0.f) ? 1.0f / s : 1.0f;
    __syncthreads();

    for (int idx = tid; idx < 256 * 64; idx += 256) {
        int r = idx >> 6;
        out[base * 64 + idx] *= inv_s[r];
    }
}

// ---------------- launch ------------------------------------------------------
extern "C" void kernel_launch(void* const* d_in, const int* in_sizes, int n_in,
                              void* d_out, int out_size) {
    const float* inputs = (const float*)d_in[0];
    const float* ids    = (const float*)d_in[1];
    const float* enh    = (const float*)d_in[2];
    const float* inh    = (const float*)d_in[3];
    const float* beta   = (const float*)d_in[4];
    const float* delta  = (const float*)d_in[5];

    cudaFuncSetAttribute(warm_kernel,
                         cudaFuncAttributeNonPortableClusterSizeAllowed, 1);
    cudaFuncSetAttribute(warm_kernel,
                         cudaFuncAttributeMaxDynamicSharedMemorySize, WARM_SMEM);
    cudaFuncSetAttribute(gemm_kernel,
                         cudaFuncAttributeMaxDynamicSharedMemorySize, SMEM_GEMM);

    warm_kernel<<<CB, 256, WARM_SMEM>>>(ids, enh, inh, beta, delta);

    dim3 grid(BROWS / TM, 8);
    gemm_kernel<<<grid, 256, SMEM_GEMM>>>(inputs, (float*)d_out);

    scale_kernel<<<BROWS / 256, 256>>>((float*)d_out);
}